// round 3
// baseline (speedup 1.0000x reference)
#include <cuda_runtime.h>

#define BB 4
#define TT 2048
#define DD 1024
#define HH 16
#define HD 64
#define MROWS (BB*TT)   // 8192

// scratch: [B,H,T,HD] layouts
__device__ float g_q[BB*HH*TT*HD];
__device__ float g_k[BB*HH*TT*HD];
__device__ float g_v[BB*HH*TT*HD];
__device__ float g_attn[BB*HH*TT*HD];

// ---------------------------------------------------------------------------
// GEMM 1: qkv = x @ W_qkv + b_qkv, scatter into q/k/v head-major buffers
// C[8192, 3072] ; 128x128 tile, BK=8, 256 threads, 8x8 per thread
// ---------------------------------------------------------------------------
__global__ __launch_bounds__(256) void gemm_qkv_kernel(
    const float* __restrict__ X, const float* __restrict__ W,
    const float* __restrict__ bias)
{
    constexpr int K = DD;
    constexpr int N = 3 * DD;
    __shared__ float As[8][128];
    __shared__ float Bs[8][128];

    const int tid = threadIdx.x;
    const int tx = tid & 15, ty = tid >> 4;
    const int mtile = blockIdx.y * 128;
    const int ntile = blockIdx.x * 128;

    float acc[8][8];
#pragma unroll
    for (int i = 0; i < 8; ++i)
#pragma unroll
        for (int j = 0; j < 8; ++j) acc[i][j] = 0.f;

    const int arow = tid >> 1, acol = (tid & 1) * 4;
    const int brow = tid >> 5, bcol = (tid & 31) * 4;
    const float* Aptr = X + (size_t)(mtile + arow) * K + acol;
    const float* Bptr = W + (size_t)brow * N + ntile + bcol;

    for (int k0 = 0; k0 < K; k0 += 8) {
        __syncthreads();
        float4 av = *(const float4*)(Aptr + k0);
        As[acol + 0][arow] = av.x;
        As[acol + 1][arow] = av.y;
        As[acol + 2][arow] = av.z;
        As[acol + 3][arow] = av.w;
        *(float4*)&Bs[brow][bcol] = *(const float4*)(Bptr + (size_t)k0 * N);
        __syncthreads();
#pragma unroll
        for (int kk = 0; kk < 8; ++kk) {
            float4 a0 = *(const float4*)&As[kk][ty * 4];
            float4 a1 = *(const float4*)&As[kk][ty * 4 + 64];
            float4 b0 = *(const float4*)&Bs[kk][tx * 4];
            float4 b1 = *(const float4*)&Bs[kk][tx * 4 + 64];
            float a[8] = {a0.x, a0.y, a0.z, a0.w, a1.x, a1.y, a1.z, a1.w};
            float b[8] = {b0.x, b0.y, b0.z, b0.w, b1.x, b1.y, b1.z, b1.w};
#pragma unroll
            for (int i = 0; i < 8; ++i)
#pragma unroll
                for (int j = 0; j < 8; ++j) acc[i][j] += a[i] * b[j];
        }
    }

#pragma unroll
    for (int i = 0; i < 8; ++i) {
        const int mrow = mtile + ty * 4 + (i & 3) + (i >> 2) * 64;
        const int b_ = mrow >> 11;        // / 2048
        const int t_ = mrow & 2047;
#pragma unroll
        for (int j = 0; j < 8; ++j) {
            const int ncol = ntile + tx * 4 + (j & 3) + (j >> 2) * 64;
            const float val = acc[i][j] + bias[ncol];
            const int which = ncol >> 10;     // 0=q 1=k 2=v
            const int dcol = ncol & 1023;
            const int h_ = dcol >> 6, hd_ = dcol & 63;
            float* dst = (which == 0) ? g_q : (which == 1) ? g_k : g_v;
            dst[(((size_t)b_ * HH + h_) * TT + t_) * HD + hd_] = val;
        }
    }
}

// ---------------------------------------------------------------------------
// Flash attention (causal). One thread per q row; 128 rows per block.
// K/V tiles of 64 keys in smem, broadcast float4 LDS.
// ---------------------------------------------------------------------------
#define BKV 64
__global__ __launch_bounds__(128) void attn_kernel()
{
    const int bh = blockIdx.y;       // 0..63  (b*H + h)
    const int qtile = blockIdx.x;    // 0..15
    const int tidx = threadIdx.x;    // 0..127
    const int qrow = qtile * 128 + tidx;

    const float* Qb = g_q + (size_t)bh * TT * HD;
    const float* Kb = g_k + (size_t)bh * TT * HD;
    const float* Vb = g_v + (size_t)bh * TT * HD;

    float q[HD];
    {
        const float4* qp = (const float4*)(Qb + (size_t)qrow * HD);
#pragma unroll
        for (int dd = 0; dd < 16; ++dd) {
            float4 v = qp[dd];
            q[4 * dd + 0] = v.x * 0.125f;  // fold 1/sqrt(64)
            q[4 * dd + 1] = v.y * 0.125f;
            q[4 * dd + 2] = v.z * 0.125f;
            q[4 * dd + 3] = v.w * 0.125f;
        }
    }

    float acc[HD];
#pragma unroll
    for (int d = 0; d < HD; ++d) acc[d] = 0.f;
    float m = -1e30f, l = 0.f;

    __shared__ float Ks[BKV][HD];
    __shared__ float Vs[BKV][HD];

    const int kend = (qtile + 1) * 128;   // causal: keys < kend
    for (int k0 = 0; k0 < kend; k0 += BKV) {
        __syncthreads();
        {
            const float4* kg = (const float4*)(Kb + (size_t)k0 * HD);
            const float4* vg = (const float4*)(Vb + (size_t)k0 * HD);
            float4* ks = (float4*)&Ks[0][0];
            float4* vs = (float4*)&Vs[0][0];
#pragma unroll
            for (int i = 0; i < BKV * HD / 4 / 128; ++i) {   // 8
                ks[tidx + i * 128] = kg[tidx + i * 128];
                vs[tidx + i * 128] = vg[tidx + i * 128];
            }
        }
        __syncthreads();

        if (k0 <= qrow) {
            float s[BKV];
            for (int j = 0; j < BKV; ++j) {
                const float4* kr = (const float4*)&Ks[j][0];
                float s0 = 0.f, s1 = 0.f, s2 = 0.f, s3 = 0.f;
#pragma unroll
                for (int dd = 0; dd < 16; ++dd) {
                    float4 kv = kr[dd];
                    s0 += q[4 * dd + 0] * kv.x;
                    s1 += q[4 * dd + 1] * kv.y;
                    s2 += q[4 * dd + 2] * kv.z;
                    s3 += q[4 * dd + 3] * kv.w;
                }
                s[j] = (s0 + s1) + (s2 + s3);
            }
            float tmax = m;
#pragma unroll
            for (int j = 0; j < BKV; ++j) {
                if (k0 + j > qrow) s[j] = -1e30f;
                tmax = fmaxf(tmax, s[j]);
            }
            const float corr = __expf(m - tmax);
            m = tmax;
            l *= corr;
#pragma unroll
            for (int d = 0; d < HD; ++d) acc[d] *= corr;
            for (int j = 0; j < BKV; ++j) {
                const float p = __expf(s[j] - m);
                l += p;
                const float4* vr = (const float4*)&Vs[j][0];
#pragma unroll
                for (int dd = 0; dd < 16; ++dd) {
                    float4 vv = vr[dd];
                    acc[4 * dd + 0] += p * vv.x;
                    acc[4 * dd + 1] += p * vv.y;
                    acc[4 * dd + 2] += p * vv.z;
                    acc[4 * dd + 3] += p * vv.w;
                }
            }
        }
    }

    const float inv = 1.0f / l;
    float4* outp = (float4*)(g_attn + ((size_t)bh * TT + qrow) * HD);
#pragma unroll
    for (int dd = 0; dd < 16; ++dd) {
        outp[dd] = make_float4(acc[4 * dd + 0] * inv, acc[4 * dd + 1] * inv,
                               acc[4 * dd + 2] * inv, acc[4 * dd + 3] * inv);
    }
}

// ---------------------------------------------------------------------------
// GEMM 2: out = attn_heads @ W_out + b_out (A gathered from head-major layout)
// C[8192, 1024]
// ---------------------------------------------------------------------------
__global__ __launch_bounds__(256) void gemm_out_kernel(
    const float* __restrict__ W, const float* __restrict__ bias,
    float* __restrict__ Out)
{
    constexpr int K = DD;
    constexpr int N = DD;
    __shared__ float As[8][128];
    __shared__ float Bs[8][128];

    const int tid = threadIdx.x;
    const int tx = tid & 15, ty = tid >> 4;
    const int mtile = blockIdx.y * 128;
    const int ntile = blockIdx.x * 128;

    float acc[8][8];
#pragma unroll
    for (int i = 0; i < 8; ++i)
#pragma unroll
        for (int j = 0; j < 8; ++j) acc[i][j] = 0.f;

    const int arow = tid >> 1, acol = (tid & 1) * 4;
    const int brow = tid >> 5, bcol = (tid & 31) * 4;
    const int amrow = mtile + arow;
    const int ab = amrow >> 11, at = amrow & 2047;
    const float* Bptr = W + (size_t)brow * N + ntile + bcol;

    for (int k0 = 0; k0 < K; k0 += 8) {
        __syncthreads();
        {
            const int k = k0 + acol;
            const int h_ = k >> 6, hd_ = k & 63;
            float4 av = *(const float4*)(g_attn +
                (((size_t)ab * HH + h_) * TT + at) * HD + hd_);
            As[acol + 0][arow] = av.x;
            As[acol + 1][arow] = av.y;
            As[acol + 2][arow] = av.z;
            As[acol + 3][arow] = av.w;
        }
        *(float4*)&Bs[brow][bcol] = *(const float4*)(Bptr + (size_t)k0 * N);
        __syncthreads();
#pragma unroll
        for (int kk = 0; kk < 8; ++kk) {
            float4 a0 = *(const float4*)&As[kk][ty * 4];
            float4 a1 = *(const float4*)&As[kk][ty * 4 + 64];
            float4 b0 = *(const float4*)&Bs[kk][tx * 4];
            float4 b1 = *(const float4*)&Bs[kk][tx * 4 + 64];
            float a[8] = {a0.x, a0.y, a0.z, a0.w, a1.x, a1.y, a1.z, a1.w};
            float b[8] = {b0.x, b0.y, b0.z, b0.w, b1.x, b1.y, b1.z, b1.w};
#pragma unroll
            for (int i = 0; i < 8; ++i)
#pragma unroll
                for (int j = 0; j < 8; ++j) acc[i][j] += a[i] * b[j];
        }
    }

#pragma unroll
    for (int i = 0; i < 8; ++i) {
        const int mrow = mtile + ty * 4 + (i & 3) + (i >> 2) * 64;
#pragma unroll
        for (int j = 0; j < 8; ++j) {
            const int ncol = ntile + tx * 4 + (j & 3) + (j >> 2) * 64;
            Out[(size_t)mrow * N + ncol] = acc[i][j] + bias[ncol];
        }
    }
}

// ---------------------------------------------------------------------------
extern "C" void kernel_launch(void* const* d_in, const int* in_sizes, int n_in,
                              void* d_out, int out_size)
{
    const float* x     = (const float*)d_in[0];
    const float* W_qkv = (const float*)d_in[1];
    const float* b_qkv = (const float*)d_in[2];
    const float* W_out = (const float*)d_in[3];
    const float* b_out = (const float*)d_in[4];
    float* out = (float*)d_out;

    // qkv projection: C[8192,3072]
    {
        dim3 grid(3 * DD / 128, MROWS / 128);   // (24, 64)
        gemm_qkv_kernel<<<grid, 256>>>(x, W_qkv, b_qkv);
    }
    // attention
    {
        dim3 grid(TT / 128, BB * HH);           // (16, 64)
        attn_kernel<<<grid, 128>>>();
    }
    // output projection: C[8192,1024]
    {
        dim3 grid(DD / 128, MROWS / 128);       // (8, 64)
        gemm_out_kernel<<<grid, 256>>>(W_out, b_out, out);
    }
}

// round 5
// speedup vs baseline: 2.6579x; 2.6579x over previous
#include <cuda_runtime.h>
#include <cstdint>

#define BB 4
#define TT 2048
#define DD 1024
#define HH 16
#define HD 64
#define MROWS (BB*TT)   // 8192

// scratch
__device__ float g_q[BB*HH*TT*HD];     // [b,h,t,hd]
__device__ float g_k[BB*HH*TT*HD];     // [b,h,t,hd]
__device__ float g_v[BB*HH*TT*HD];     // [b,h,t,hd]
__device__ float g_attn[BB*TT*DD];     // [b,t,h,hd] == row-major [M][K]

// ---------------------------------------------------------------------------
// tf32 helpers
// ---------------------------------------------------------------------------
__device__ __forceinline__ float to_tf32(float x) {
    uint32_t r;
    asm("cvt.rna.tf32.f32 %0, %1;" : "=r"(r) : "f"(x));
    return __uint_as_float(r);
}

__device__ __forceinline__ void mma_tf32(float* c, const uint32_t* a, const uint32_t* b) {
    asm volatile(
        "mma.sync.aligned.m16n8k8.row.col.f32.tf32.tf32.f32 "
        "{%0,%1,%2,%3}, {%4,%5,%6,%7}, {%8,%9}, {%0,%1,%2,%3};"
        : "+f"(c[0]), "+f"(c[1]), "+f"(c[2]), "+f"(c[3])
        : "r"(a[0]), "r"(a[1]), "r"(a[2]), "r"(a[3]), "r"(b[0]), "r"(b[1]));
}

// ---------------------------------------------------------------------------
// GEMM 1 (tensor cores, tf32): qkv = x @ W_qkv + b_qkv -> scatter q/k/v
// M=8192, K=1024, N=3072. Tile 128x128xBK32, 8 warps (4x2), 32x64 per warp.
// ---------------------------------------------------------------------------
__global__ __launch_bounds__(256) void gemm_qkv_tc(
    const float* __restrict__ X, const float* __restrict__ W,
    const float* __restrict__ bias)
{
    constexpr int K = DD;
    constexpr int N = 3 * DD;
    __shared__ float As[128][36];   // [m][k], pad 36 -> frag banks 4r+c (conflict-free)
    __shared__ float Bs[32][136];   // [k][n], pad 136 -> frag banks 8c+r (conflict-free)

    const int tid = threadIdx.x;
    const int lane = tid & 31;
    const int wid = tid >> 5;
    const int wm = wid >> 1;        // 0..3
    const int wn = wid & 1;         // 0..1
    const int mtile = blockIdx.y * 128;
    const int ntile = blockIdx.x * 128;

    float c[2][8][4];
#pragma unroll
    for (int mt = 0; mt < 2; ++mt)
#pragma unroll
        for (int nt = 0; nt < 8; ++nt)
#pragma unroll
            for (int i = 0; i < 4; ++i) c[mt][nt][i] = 0.f;

    const int lm = tid >> 3;        // 0..31 (A load row)
    const int lj = tid & 7;         // A load float4 col
    const int bkr = tid >> 5;       // 0..7  (B load row)
    const int bnj = tid & 31;       // B load float4 col

    const int gr = lane >> 2;       // fragment group row 0..7
    const int gc = lane & 3;        // fragment group col 0..3

    for (int k0 = 0; k0 < K; k0 += 32) {
        // load A tile -> As[m][k] (tf32-rounded)
#pragma unroll
        for (int it = 0; it < 4; ++it) {
            const int m = lm + 32 * it;
            float4 v = *(const float4*)(X + (size_t)(mtile + m) * K + k0 + 4 * lj);
            float4 t = make_float4(to_tf32(v.x), to_tf32(v.y), to_tf32(v.z), to_tf32(v.w));
            *(float4*)&As[m][4 * lj] = t;
        }
        // load B tile -> Bs[k][n]
#pragma unroll
        for (int it = 0; it < 4; ++it) {
            const int kr = bkr + 8 * it;
            float4 v = *(const float4*)(W + (size_t)(k0 + kr) * N + ntile + 4 * bnj);
            float4 t = make_float4(to_tf32(v.x), to_tf32(v.y), to_tf32(v.z), to_tf32(v.w));
            *(float4*)&Bs[kr][4 * bnj] = t;
        }
        __syncthreads();

#pragma unroll
        for (int ks = 0; ks < 4; ++ks) {
            const int kk = ks * 8;
            uint32_t a[2][4];
#pragma unroll
            for (int mt = 0; mt < 2; ++mt) {
                const int r = wm * 32 + mt * 16 + gr;
                a[mt][0] = __float_as_uint(As[r][kk + gc]);
                a[mt][1] = __float_as_uint(As[r + 8][kk + gc]);
                a[mt][2] = __float_as_uint(As[r][kk + gc + 4]);
                a[mt][3] = __float_as_uint(As[r + 8][kk + gc + 4]);
            }
            uint32_t b[8][2];
#pragma unroll
            for (int nt = 0; nt < 8; ++nt) {
                const int n = wn * 64 + nt * 8 + gr;
                b[nt][0] = __float_as_uint(Bs[kk + gc][n]);
                b[nt][1] = __float_as_uint(Bs[kk + gc + 4][n]);
            }
#pragma unroll
            for (int mt = 0; mt < 2; ++mt)
#pragma unroll
                for (int nt = 0; nt < 8; ++nt)
                    mma_tf32(c[mt][nt], a[mt], b[nt]);
        }
        __syncthreads();
    }

    // epilogue: bias + scatter to q/k/v [b,h,t,hd]
#pragma unroll
    for (int mt = 0; mt < 2; ++mt) {
        const int r0 = mtile + wm * 32 + mt * 16 + gr;
#pragma unroll
        for (int nt = 0; nt < 8; ++nt) {
            const int col = ntile + wn * 64 + nt * 8 + gc * 2;
            const float bz0 = bias[col], bz1 = bias[col + 1];
            const int which = col >> 10;
            const int dcol = col & 1023;
            const int h_ = dcol >> 6, hd_ = dcol & 63;
            float* dst = (which == 0) ? g_q : (which == 1) ? g_k : g_v;
#pragma unroll
            for (int half = 0; half < 2; ++half) {
                const int row = r0 + half * 8;
                const int b_ = row >> 11, t_ = row & 2047;
                float2 v = make_float2(c[mt][nt][2 * half + 0] + bz0,
                                       c[mt][nt][2 * half + 1] + bz1);
                *(float2*)&dst[(((size_t)b_ * HH + h_) * TT + t_) * HD + hd_] = v;
            }
        }
    }
}

// ---------------------------------------------------------------------------
// Flash attention (causal, fp32 scalar). One thread per q row; 128 rows/block.
// Output written to g_attn in [b,t,h,hd] (row-major [M][K] for out-proj).
// ---------------------------------------------------------------------------
#define BKV 64
__global__ __launch_bounds__(128) void attn_kernel()
{
    const int bh = blockIdx.y;
    const int qtile = blockIdx.x;
    const int tidx = threadIdx.x;
    const int qrow = qtile * 128 + tidx;

    const float* Qb = g_q + (size_t)bh * TT * HD;
    const float* Kb = g_k + (size_t)bh * TT * HD;
    const float* Vb = g_v + (size_t)bh * TT * HD;

    float q[HD];
    {
        const float4* qp = (const float4*)(Qb + (size_t)qrow * HD);
#pragma unroll
        for (int dd = 0; dd < 16; ++dd) {
            float4 v = qp[dd];
            q[4 * dd + 0] = v.x * 0.125f;
            q[4 * dd + 1] = v.y * 0.125f;
            q[4 * dd + 2] = v.z * 0.125f;
            q[4 * dd + 3] = v.w * 0.125f;
        }
    }

    float acc[HD];
#pragma unroll
    for (int d = 0; d < HD; ++d) acc[d] = 0.f;
    float m = -1e30f, l = 0.f;

    __shared__ float Ks[BKV][HD];
    __shared__ float Vs[BKV][HD];

    const int kend = (qtile + 1) * 128;
    for (int k0 = 0; k0 < kend; k0 += BKV) {
        __syncthreads();
        {
            const float4* kg = (const float4*)(Kb + (size_t)k0 * HD);
            const float4* vg = (const float4*)(Vb + (size_t)k0 * HD);
            float4* ks = (float4*)&Ks[0][0];
            float4* vs = (float4*)&Vs[0][0];
#pragma unroll
            for (int i = 0; i < BKV * HD / 4 / 128; ++i) {
                ks[tidx + i * 128] = kg[tidx + i * 128];
                vs[tidx + i * 128] = vg[tidx + i * 128];
            }
        }
        __syncthreads();

        if (k0 <= qrow) {
            float s[BKV];
            for (int j = 0; j < BKV; ++j) {
                const float4* kr = (const float4*)&Ks[j][0];
                float s0 = 0.f, s1 = 0.f, s2 = 0.f, s3 = 0.f;
#pragma unroll
                for (int dd = 0; dd < 16; ++dd) {
                    float4 kv = kr[dd];
                    s0 += q[4 * dd + 0] * kv.x;
                    s1 += q[4 * dd + 1] * kv.y;
                    s2 += q[4 * dd + 2] * kv.z;
                    s3 += q[4 * dd + 3] * kv.w;
                }
                s[j] = (s0 + s1) + (s2 + s3);
            }
            float tmax = m;
#pragma unroll
            for (int j = 0; j < BKV; ++j) {
                if (k0 + j > qrow) s[j] = -1e30f;
                tmax = fmaxf(tmax, s[j]);
            }
            const float corr = __expf(m - tmax);
            m = tmax;
            l *= corr;
#pragma unroll
            for (int d = 0; d < HD; ++d) acc[d] *= corr;
            for (int j = 0; j < BKV; ++j) {
                const float p = __expf(s[j] - m);
                l += p;
                const float4* vr = (const float4*)&Vs[j][0];
#pragma unroll
                for (int dd = 0; dd < 16; ++dd) {
                    float4 vv = vr[dd];
                    acc[4 * dd + 0] += p * vv.x;
                    acc[4 * dd + 1] += p * vv.y;
                    acc[4 * dd + 2] += p * vv.z;
                    acc[4 * dd + 3] += p * vv.w;
                }
            }
        }
    }

    const float inv = 1.0f / l;
    const int b_ = bh >> 4, h_ = bh & 15;
    float4* outp = (float4*)(g_attn + (((size_t)b_ * TT + qrow) * HH + h_) * HD);
#pragma unroll
    for (int dd = 0; dd < 16; ++dd) {
        outp[dd] = make_float4(acc[4 * dd + 0] * inv, acc[4 * dd + 1] * inv,
                               acc[4 * dd + 2] * inv, acc[4 * dd + 3] * inv);
    }
}

// ---------------------------------------------------------------------------
// GEMM 2 (tensor cores, tf32): out = attn @ W_out + b_out
// M=8192, K=1024, N=1024. Same structure; A = g_attn row-major.
// ---------------------------------------------------------------------------
__global__ __launch_bounds__(256) void gemm_out_tc(
    const float* __restrict__ W, const float* __restrict__ bias,
    float* __restrict__ Out)
{
    constexpr int K = DD;
    constexpr int N = DD;
    __shared__ float As[128][36];
    __shared__ float Bs[32][136];

    const int tid = threadIdx.x;
    const int lane = tid & 31;
    const int wid = tid >> 5;
    const int wm = wid >> 1;
    const int wn = wid & 1;
    const int mtile = blockIdx.y * 128;
    const int ntile = blockIdx.x * 128;

    float c[2][8][4];
#pragma unroll
    for (int mt = 0; mt < 2; ++mt)
#pragma unroll
        for (int nt = 0; nt < 8; ++nt)
#pragma unroll
            for (int i = 0; i < 4; ++i) c[mt][nt][i] = 0.f;

    const int lm = tid >> 3;
    const int lj = tid & 7;
    const int bkr = tid >> 5;
    const int bnj = tid & 31;
    const int gr = lane >> 2;
    const int gc = lane & 3;

    for (int k0 = 0; k0 < K; k0 += 32) {
#pragma unroll
        for (int it = 0; it < 4; ++it) {
            const int m = lm + 32 * it;
            float4 v = *(const float4*)(g_attn + (size_t)(mtile + m) * K + k0 + 4 * lj);
            float4 t = make_float4(to_tf32(v.x), to_tf32(v.y), to_tf32(v.z), to_tf32(v.w));
            *(float4*)&As[m][4 * lj] = t;
        }
#pragma unroll
        for (int it = 0; it < 4; ++it) {
            const int kr = bkr + 8 * it;
            float4 v = *(const float4*)(W + (size_t)(k0 + kr) * N + ntile + 4 * bnj);
            float4 t = make_float4(to_tf32(v.x), to_tf32(v.y), to_tf32(v.z), to_tf32(v.w));
            *(float4*)&Bs[kr][4 * bnj] = t;
        }
        __syncthreads();

#pragma unroll
        for (int ks = 0; ks < 4; ++ks) {
            const int kk = ks * 8;
            uint32_t a[2][4];
#pragma unroll
            for (int mt = 0; mt < 2; ++mt) {
                const int r = wm * 32 + mt * 16 + gr;
                a[mt][0] = __float_as_uint(As[r][kk + gc]);
                a[mt][1] = __float_as_uint(As[r + 8][kk + gc]);
                a[mt][2] = __float_as_uint(As[r][kk + gc + 4]);
                a[mt][3] = __float_as_uint(As[r + 8][kk + gc + 4]);
            }
            uint32_t b[8][2];
#pragma unroll
            for (int nt = 0; nt < 8; ++nt) {
                const int n = wn * 64 + nt * 8 + gr;
                b[nt][0] = __float_as_uint(Bs[kk + gc][n]);
                b[nt][1] = __float_as_uint(Bs[kk + gc + 4][n]);
            }
#pragma unroll
            for (int mt = 0; mt < 2; ++mt)
#pragma unroll
                for (int nt = 0; nt < 8; ++nt)
                    mma_tf32(c[mt][nt], a[mt], b[nt]);
        }
        __syncthreads();
    }

#pragma unroll
    for (int mt = 0; mt < 2; ++mt) {
        const int r0 = mtile + wm * 32 + mt * 16 + gr;
#pragma unroll
        for (int nt = 0; nt < 8; ++nt) {
            const int col = ntile + wn * 64 + nt * 8 + gc * 2;
            const float bz0 = bias[col], bz1 = bias[col + 1];
#pragma unroll
            for (int half = 0; half < 2; ++half) {
                const int row = r0 + half * 8;
                float2 v = make_float2(c[mt][nt][2 * half + 0] + bz0,
                                       c[mt][nt][2 * half + 1] + bz1);
                *(float2*)&Out[(size_t)row * N + col] = v;
            }
        }
    }
}

// ---------------------------------------------------------------------------
extern "C" void kernel_launch(void* const* d_in, const int* in_sizes, int n_in,
                              void* d_out, int out_size)
{
    const float* x     = (const float*)d_in[0];
    const float* W_qkv = (const float*)d_in[1];
    const float* b_qkv = (const float*)d_in[2];
    const float* W_out = (const float*)d_in[3];
    const float* b_out = (const float*)d_in[4];
    float* out = (float*)d_out;

    {
        dim3 grid(3 * DD / 128, MROWS / 128);   // (24, 64)
        gemm_qkv_tc<<<grid, 256>>>(x, W_qkv, b_qkv);
    }
    {
        dim3 grid(TT / 128, BB * HH);           // (16, 64)
        attn_kernel<<<grid, 128>>>();
    }
    {
        dim3 grid(DD / 128, MROWS / 128);       // (8, 64)
        gemm_out_tc<<<grid, 256>>>(W_out, b_out, out);
    }
}

// round 7
// speedup vs baseline: 6.6596x; 2.5056x over previous
#include <cuda_runtime.h>
#include <cstdint>

#define BB 4
#define TT 2048
#define DD 1024
#define HH 16
#define HD 64
#define MROWS (BB*TT)   // 8192

// scratch
__device__ float g_q[BB*HH*TT*HD];     // [b,h,t,hd]
__device__ float g_k[BB*HH*TT*HD];     // [b,h,t,hd]
__device__ float g_v[BB*HH*TT*HD];     // [b,h,t,hd]
__device__ float g_attn[BB*TT*DD];     // [b,t,h,hd] == row-major [M][K]

// ---------------------------------------------------------------------------
// helpers
// ---------------------------------------------------------------------------
__device__ __forceinline__ float to_tf32(float x) {
    uint32_t r;
    asm("cvt.rna.tf32.f32 %0, %1;" : "=r"(r) : "f"(x));
    return __uint_as_float(r);
}
__device__ __forceinline__ uint32_t tf32_bits(float x) {
    uint32_t r;
    asm("cvt.rna.tf32.f32 %0, %1;" : "=r"(r) : "f"(x));
    return r;
}
__device__ __forceinline__ float ex2(float x) {
    float r;
    asm("ex2.approx.f32 %0, %1;" : "=f"(r) : "f"(x));
    return r;
}
__device__ __forceinline__ void mma_tf32(float* c, const uint32_t* a, const uint32_t* b) {
    asm volatile(
        "mma.sync.aligned.m16n8k8.row.col.f32.tf32.tf32.f32 "
        "{%0,%1,%2,%3}, {%4,%5,%6,%7}, {%8,%9}, {%0,%1,%2,%3};"
        : "+f"(c[0]), "+f"(c[1]), "+f"(c[2]), "+f"(c[3])
        : "r"(a[0]), "r"(a[1]), "r"(a[2]), "r"(a[3]), "r"(b[0]), "r"(b[1]));
}

// ---------------------------------------------------------------------------
// GEMM 1 (tensor cores, tf32): qkv = x @ W_qkv + b_qkv -> scatter q/k/v
// ---------------------------------------------------------------------------
__global__ __launch_bounds__(256) void gemm_qkv_tc(
    const float* __restrict__ X, const float* __restrict__ W,
    const float* __restrict__ bias)
{
    constexpr int K = DD;
    constexpr int N = 3 * DD;
    __shared__ float As[128][36];
    __shared__ float Bs[32][136];

    const int tid = threadIdx.x;
    const int lane = tid & 31;
    const int wid = tid >> 5;
    const int wm = wid >> 1;
    const int wn = wid & 1;
    const int mtile = blockIdx.y * 128;
    const int ntile = blockIdx.x * 128;

    float c[2][8][4];
#pragma unroll
    for (int mt = 0; mt < 2; ++mt)
#pragma unroll
        for (int nt = 0; nt < 8; ++nt)
#pragma unroll
            for (int i = 0; i < 4; ++i) c[mt][nt][i] = 0.f;

    const int lm = tid >> 3;
    const int lj = tid & 7;
    const int bkr = tid >> 5;
    const int bnj = tid & 31;
    const int gr = lane >> 2;
    const int gc = lane & 3;

    for (int k0 = 0; k0 < K; k0 += 32) {
#pragma unroll
        for (int it = 0; it < 4; ++it) {
            const int m = lm + 32 * it;
            float4 v = *(const float4*)(X + (size_t)(mtile + m) * K + k0 + 4 * lj);
            float4 t = make_float4(to_tf32(v.x), to_tf32(v.y), to_tf32(v.z), to_tf32(v.w));
            *(float4*)&As[m][4 * lj] = t;
        }
#pragma unroll
        for (int it = 0; it < 4; ++it) {
            const int kr = bkr + 8 * it;
            float4 v = *(const float4*)(W + (size_t)(k0 + kr) * N + ntile + 4 * bnj);
            float4 t = make_float4(to_tf32(v.x), to_tf32(v.y), to_tf32(v.z), to_tf32(v.w));
            *(float4*)&Bs[kr][4 * bnj] = t;
        }
        __syncthreads();

#pragma unroll
        for (int ks = 0; ks < 4; ++ks) {
            const int kk = ks * 8;
            uint32_t a[2][4];
#pragma unroll
            for (int mt = 0; mt < 2; ++mt) {
                const int r = wm * 32 + mt * 16 + gr;
                a[mt][0] = __float_as_uint(As[r][kk + gc]);
                a[mt][1] = __float_as_uint(As[r + 8][kk + gc]);
                a[mt][2] = __float_as_uint(As[r][kk + gc + 4]);
                a[mt][3] = __float_as_uint(As[r + 8][kk + gc + 4]);
            }
            uint32_t b[8][2];
#pragma unroll
            for (int nt = 0; nt < 8; ++nt) {
                const int n = wn * 64 + nt * 8 + gr;
                b[nt][0] = __float_as_uint(Bs[kk + gc][n]);
                b[nt][1] = __float_as_uint(Bs[kk + gc + 4][n]);
            }
#pragma unroll
            for (int mt = 0; mt < 2; ++mt)
#pragma unroll
                for (int nt = 0; nt < 8; ++nt)
                    mma_tf32(c[mt][nt], a[mt], b[nt]);
        }
        __syncthreads();
    }

#pragma unroll
    for (int mt = 0; mt < 2; ++mt) {
        const int r0 = mtile + wm * 32 + mt * 16 + gr;
#pragma unroll
        for (int nt = 0; nt < 8; ++nt) {
            const int col = ntile + wn * 64 + nt * 8 + gc * 2;
            const float bz0 = bias[col], bz1 = bias[col + 1];
            const int which = col >> 10;
            const int dcol = col & 1023;
            const int h_ = dcol >> 6, hd_ = dcol & 63;
            float* dst = (which == 0) ? g_q : (which == 1) ? g_k : g_v;
#pragma unroll
            for (int half = 0; half < 2; ++half) {
                const int row = r0 + half * 8;
                const int b_ = row >> 11, t_ = row & 2047;
                float2 v = make_float2(c[mt][nt][2 * half + 0] + bz0,
                                       c[mt][nt][2 * half + 1] + bz1);
                *(float2*)&dst[(((size_t)b_ * HH + h_) * TT + t_) * HD + hd_] = v;
            }
        }
    }
}

// ---------------------------------------------------------------------------
// Flash attention (causal) on tensor cores (tf32 mma).
// 256 threads = 8 warps; warp owns 16 q-rows x full KV tile (64 keys).
// K smem stride 68, V smem stride 72 -> conflict-free B-fragment LDS.
// ---------------------------------------------------------------------------
#define BKV 64
#define KSTR 68
#define VSTR 72

__global__ __launch_bounds__(256) void attn_tc_kernel()
{
    const int bh = blockIdx.y;       // b*H+h
    const int qtile = blockIdx.x;    // 0..15
    const int tid = threadIdx.x;
    const int lane = tid & 31;
    const int warp = tid >> 5;       // 0..7
    const int gr = lane >> 2;        // 0..7
    const int gc = lane & 3;         // 0..3

    const int qbase = qtile * 128;
    const int row0 = qbase + warp * 16 + gr;   // rows row0, row0+8

    const float* Qb = g_q + (size_t)bh * TT * HD;
    const float* Kb = g_k + (size_t)bh * TT * HD;
    const float* Vb = g_v + (size_t)bh * TT * HD;

    __shared__ float Ks[BKV][KSTR];
    __shared__ float Vs[BKV][VSTR];

    // Q fragments (persistent, scaled by 1/8 * log2(e), tf32)
    const float QSCALE = 0.125f * 1.4426950408889634f;
    uint32_t qf[8][4];
#pragma unroll
    for (int ks = 0; ks < 8; ++ks) {
        const int kk = ks * 8;
        qf[ks][0] = tf32_bits(Qb[(size_t)row0 * HD + kk + gc] * QSCALE);
        qf[ks][1] = tf32_bits(Qb[(size_t)(row0 + 8) * HD + kk + gc] * QSCALE);
        qf[ks][2] = tf32_bits(Qb[(size_t)row0 * HD + kk + gc + 4] * QSCALE);
        qf[ks][3] = tf32_bits(Qb[(size_t)(row0 + 8) * HD + kk + gc + 4] * QSCALE);
    }

    float o[8][4];
#pragma unroll
    for (int nt = 0; nt < 8; ++nt)
#pragma unroll
        for (int i = 0; i < 4; ++i) o[nt][i] = 0.f;
    float m0 = -1e30f, m1 = -1e30f;   // row max (rows row0, row0+8)
    float l0 = 0.f, l1 = 0.f;         // per-lane partial row sums

    const int kend = qbase + 128;
    for (int k0 = 0; k0 < kend; k0 += BKV) {
        // ---- load K/V tile (coalesced float4, tf32-rounded at store) ----
        __syncthreads();
        {
            const int r = tid >> 4;          // 0..15
            const int c4 = (tid & 15) * 4;   // 0..60
#pragma unroll
            for (int it = 0; it < 4; ++it) {
                const int row = r + 16 * it;
                float4 kv = *(const float4*)(Kb + (size_t)(k0 + row) * HD + c4);
                float4 vv = *(const float4*)(Vb + (size_t)(k0 + row) * HD + c4);
                *(float4*)&Ks[row][c4] = make_float4(to_tf32(kv.x), to_tf32(kv.y),
                                                     to_tf32(kv.z), to_tf32(kv.w));
                *(float4*)&Vs[row][c4] = make_float4(to_tf32(vv.x), to_tf32(vv.y),
                                                     to_tf32(vv.z), to_tf32(vv.w));
            }
        }
        __syncthreads();

        // ---- S = Q K^T  (16 x 64 per warp) ----
        float s[8][4];
#pragma unroll
        for (int nt = 0; nt < 8; ++nt)
#pragma unroll
            for (int i = 0; i < 4; ++i) s[nt][i] = 0.f;
#pragma unroll
        for (int ks = 0; ks < 8; ++ks) {
            const int kk = ks * 8;
#pragma unroll
            for (int nt = 0; nt < 8; ++nt) {
                uint32_t b[2];
                b[0] = __float_as_uint(Ks[nt * 8 + gr][kk + gc]);
                b[1] = __float_as_uint(Ks[nt * 8 + gr][kk + gc + 4]);
                mma_tf32(s[nt], qf[ks], b);
            }
        }

        // ---- causal mask (only diagonal tiles) ----
        if (k0 + BKV > qbase) {
#pragma unroll
            for (int nt = 0; nt < 8; ++nt) {
                const int col = k0 + nt * 8 + 2 * gc;
                if (col > row0)           s[nt][0] = -1e30f;
                if (col + 1 > row0)       s[nt][1] = -1e30f;
                if (col > row0 + 8)       s[nt][2] = -1e30f;
                if (col + 1 > row0 + 8)   s[nt][3] = -1e30f;
            }
        }

        // ---- row max (shuffle over 4-lane groups) ----
        float t0 = -1e30f, t1 = -1e30f;
#pragma unroll
        for (int nt = 0; nt < 8; ++nt) {
            t0 = fmaxf(t0, fmaxf(s[nt][0], s[nt][1]));
            t1 = fmaxf(t1, fmaxf(s[nt][2], s[nt][3]));
        }
        t0 = fmaxf(t0, __shfl_xor_sync(0xffffffffu, t0, 1));
        t0 = fmaxf(t0, __shfl_xor_sync(0xffffffffu, t0, 2));
        t1 = fmaxf(t1, __shfl_xor_sync(0xffffffffu, t1, 1));
        t1 = fmaxf(t1, __shfl_xor_sync(0xffffffffu, t1, 2));

        const float mn0 = fmaxf(m0, t0);
        const float mn1 = fmaxf(m1, t1);
        const float c0 = ex2(m0 - mn0);
        const float c1 = ex2(m1 - mn1);
        m0 = mn0; m1 = mn1;
        l0 *= c0; l1 *= c1;
#pragma unroll
        for (int nt = 0; nt < 8; ++nt) {
            o[nt][0] *= c0; o[nt][1] *= c0;
            o[nt][2] *= c1; o[nt][3] *= c1;
        }

        // ---- P = exp2(S - m), accumulate partial row sums, to tf32 ----
        uint32_t p[8][4];
#pragma unroll
        for (int nt = 0; nt < 8; ++nt) {
            float p0 = ex2(s[nt][0] - mn0);
            float p1 = ex2(s[nt][1] - mn0);
            float p2 = ex2(s[nt][2] - mn1);
            float p3 = ex2(s[nt][3] - mn1);
            l0 += p0 + p1;
            l1 += p2 + p3;
            p[nt][0] = tf32_bits(p0);
            p[nt][1] = tf32_bits(p1);
            p[nt][2] = tf32_bits(p2);
            p[nt][3] = tf32_bits(p3);
        }

        // ---- O += P V  (A-frag from P c-frags via shuffle transpose) ----
        const int L1 = (lane & ~3) | (gc >> 1);
        const int L2 = L1 + 2;
        const bool hi = (gc & 1);
#pragma unroll
        for (int ks = 0; ks < 8; ++ks) {
            uint32_t a[4];
            {
                uint32_t x0 = __shfl_sync(0xffffffffu, p[ks][0], L1);
                uint32_t x1 = __shfl_sync(0xffffffffu, p[ks][1], L1);
                uint32_t x2 = __shfl_sync(0xffffffffu, p[ks][2], L1);
                uint32_t x3 = __shfl_sync(0xffffffffu, p[ks][3], L1);
                a[0] = hi ? x1 : x0;
                a[1] = hi ? x3 : x2;
                uint32_t y0 = __shfl_sync(0xffffffffu, p[ks][0], L2);
                uint32_t y1 = __shfl_sync(0xffffffffu, p[ks][1], L2);
                uint32_t y2 = __shfl_sync(0xffffffffu, p[ks][2], L2);
                uint32_t y3 = __shfl_sync(0xffffffffu, p[ks][3], L2);
                a[2] = hi ? y1 : y0;
                a[3] = hi ? y3 : y2;
            }
            const int kk = ks * 8;
#pragma unroll
            for (int nt = 0; nt < 8; ++nt) {
                uint32_t b[2];
                b[0] = __float_as_uint(Vs[kk + gc][nt * 8 + gr]);
                b[1] = __float_as_uint(Vs[kk + gc + 4][nt * 8 + gr]);
                mma_tf32(o[nt], a, b);
            }
        }
    }

    // ---- finalize: reduce l over 4 lanes, normalize, store ----
    l0 += __shfl_xor_sync(0xffffffffu, l0, 1);
    l0 += __shfl_xor_sync(0xffffffffu, l0, 2);
    l1 += __shfl_xor_sync(0xffffffffu, l1, 1);
    l1 += __shfl_xor_sync(0xffffffffu, l1, 2);
    const float inv0 = 1.0f / l0;
    const float inv1 = 1.0f / l1;

    const int b_ = bh >> 4, h_ = bh & 15;
#pragma unroll
    for (int nt = 0; nt < 8; ++nt) {
        const int col = nt * 8 + 2 * gc;
        float2 v0 = make_float2(o[nt][0] * inv0, o[nt][1] * inv0);
        float2 v1 = make_float2(o[nt][2] * inv1, o[nt][3] * inv1);
        *(float2*)&g_attn[(((size_t)b_ * TT + row0) * HH + h_) * HD + col] = v0;
        *(float2*)&g_attn[(((size_t)b_ * TT + row0 + 8) * HH + h_) * HD + col] = v1;
    }
}

// ---------------------------------------------------------------------------
// GEMM 2 (tensor cores, tf32): out = attn @ W_out + b_out
// ---------------------------------------------------------------------------
__global__ __launch_bounds__(256) void gemm_out_tc(
    const float* __restrict__ W, const float* __restrict__ bias,
    float* __restrict__ Out)
{
    constexpr int K = DD;
    constexpr int N = DD;
    __shared__ float As[128][36];
    __shared__ float Bs[32][136];

    const int tid = threadIdx.x;
    const int lane = tid & 31;
    const int wid = tid >> 5;
    const int wm = wid >> 1;
    const int wn = wid & 1;
    const int mtile = blockIdx.y * 128;
    const int ntile = blockIdx.x * 128;

    float c[2][8][4];
#pragma unroll
    for (int mt = 0; mt < 2; ++mt)
#pragma unroll
        for (int nt = 0; nt < 8; ++nt)
#pragma unroll
            for (int i = 0; i < 4; ++i) c[mt][nt][i] = 0.f;

    const int lm = tid >> 3;
    const int lj = tid & 7;
    const int bkr = tid >> 5;
    const int bnj = tid & 31;
    const int gr = lane >> 2;
    const int gc = lane & 3;

    for (int k0 = 0; k0 < K; k0 += 32) {
#pragma unroll
        for (int it = 0; it < 4; ++it) {
            const int m = lm + 32 * it;
            float4 v = *(const float4*)(g_attn + (size_t)(mtile + m) * K + k0 + 4 * lj);
            float4 t = make_float4(to_tf32(v.x), to_tf32(v.y), to_tf32(v.z), to_tf32(v.w));
            *(float4*)&As[m][4 * lj] = t;
        }
#pragma unroll
        for (int it = 0; it < 4; ++it) {
            const int kr = bkr + 8 * it;
            float4 v = *(const float4*)(W + (size_t)(k0 + kr) * N + ntile + 4 * bnj);
            float4 t = make_float4(to_tf32(v.x), to_tf32(v.y), to_tf32(v.z), to_tf32(v.w));
            *(float4*)&Bs[kr][4 * bnj] = t;
        }
        __syncthreads();

#pragma unroll
        for (int ks = 0; ks < 4; ++ks) {
            const int kk = ks * 8;
            uint32_t a[2][4];
#pragma unroll
            for (int mt = 0; mt < 2; ++mt) {
                const int r = wm * 32 + mt * 16 + gr;
                a[mt][0] = __float_as_uint(As[r][kk + gc]);
                a[mt][1] = __float_as_uint(As[r + 8][kk + gc]);
                a[mt][2] = __float_as_uint(As[r][kk + gc + 4]);
                a[mt][3] = __float_as_uint(As[r + 8][kk + gc + 4]);
            }
            uint32_t b[8][2];
#pragma unroll
            for (int nt = 0; nt < 8; ++nt) {
                const int n = wn * 64 + nt * 8 + gr;
                b[nt][0] = __float_as_uint(Bs[kk + gc][n]);
                b[nt][1] = __float_as_uint(Bs[kk + gc + 4][n]);
            }
#pragma unroll
            for (int mt = 0; mt < 2; ++mt)
#pragma unroll
                for (int nt = 0; nt < 8; ++nt)
                    mma_tf32(c[mt][nt], a[mt], b[nt]);
        }
        __syncthreads();
    }

#pragma unroll
    for (int mt = 0; mt < 2; ++mt) {
        const int r0 = mtile + wm * 32 + mt * 16 + gr;
#pragma unroll
        for (int nt = 0; nt < 8; ++nt) {
            const int col = ntile + wn * 64 + nt * 8 + gc * 2;
            const float bz0 = bias[col], bz1 = bias[col + 1];
#pragma unroll
            for (int half = 0; half < 2; ++half) {
                const int row = r0 + half * 8;
                float2 v = make_float2(c[mt][nt][2 * half + 0] + bz0,
                                       c[mt][nt][2 * half + 1] + bz1);
                *(float2*)&Out[(size_t)row * N + col] = v;
            }
        }
    }
}

// ---------------------------------------------------------------------------
extern "C" void kernel_launch(void* const* d_in, const int* in_sizes, int n_in,
                              void* d_out, int out_size)
{
    const float* x     = (const float*)d_in[0];
    const float* W_qkv = (const float*)d_in[1];
    const float* b_qkv = (const float*)d_in[2];
    const float* W_out = (const float*)d_in[3];
    const float* b_out = (const float*)d_in[4];
    float* out = (float*)d_out;

    {
        dim3 grid(3 * DD / 128, MROWS / 128);   // (24, 64)
        gemm_qkv_tc<<<grid, 256>>>(x, W_qkv, b_qkv);
    }
    {
        dim3 grid(TT / 128, BB * HH);           // (16, 64)
        attn_tc_kernel<<<grid, 256>>>();
    }
    {
        dim3 grid(DD / 128, MROWS / 128);       // (8, 64)
        gemm_out_tc<<<grid, 256>>>(W_out, b_out, out);
    }
}

// round 11
// speedup vs baseline: 6.9073x; 1.0372x over previous
#include <cuda_runtime.h>
#include <cstdint>

#define BB 4
#define TT 2048
#define DD 1024
#define HH 16
#define HD 64
#define MROWS (BB*TT)   // 8192

// scratch
__device__ float g_q[BB*HH*TT*HD];     // [b,h,t,hd]
__device__ float g_k[BB*HH*TT*HD];     // [b,h,t,hd]
__device__ float g_v[BB*HH*TT*HD];     // [b,h,t,hd]
__device__ float g_attn[BB*TT*DD];     // [b,t,h,hd] == row-major [M][K]

// ---------------------------------------------------------------------------
// helpers
// ---------------------------------------------------------------------------
__device__ __forceinline__ float to_tf32(float x) {
    uint32_t r;
    asm("cvt.rna.tf32.f32 %0, %1;" : "=r"(r) : "f"(x));
    return __uint_as_float(r);
}
__device__ __forceinline__ uint32_t tf32_bits(float x) {
    uint32_t r;
    asm("cvt.rna.tf32.f32 %0, %1;" : "=r"(r) : "f"(x));
    return r;
}
__device__ __forceinline__ float ex2(float x) {
    float r;
    asm("ex2.approx.f32 %0, %1;" : "=f"(r) : "f"(x));
    return r;
}
__device__ __forceinline__ void mma_tf32(float* c, const uint32_t* a, const uint32_t* b) {
    asm volatile(
        "mma.sync.aligned.m16n8k8.row.col.f32.tf32.tf32.f32 "
        "{%0,%1,%2,%3}, {%4,%5,%6,%7}, {%8,%9}, {%0,%1,%2,%3};"
        : "+f"(c[0]), "+f"(c[1]), "+f"(c[2]), "+f"(c[3])
        : "r"(a[0]), "r"(a[1]), "r"(a[2]), "r"(a[3]), "r"(b[0]), "r"(b[1]));
}
__device__ __forceinline__ void cp_async16(void* smem_dst, const void* gsrc) {
    uint32_t sa = (uint32_t)__cvta_generic_to_shared(smem_dst);
    asm volatile("cp.async.cg.shared.global [%0], [%1], 16;" :: "r"(sa), "l"(gsrc));
}
#define CP_COMMIT()  asm volatile("cp.async.commit_group;")
#define CP_WAIT(n)   asm volatile("cp.async.wait_group %0;" :: "n"(n))

// Pipelined GEMM smem: [2][128][36] A + [2][32][136] B (floats)
#define GEMM_SMEM_FLOATS (2*128*36 + 2*32*136)
#define GEMM_SMEM_BYTES  (GEMM_SMEM_FLOATS * 4)

// ---------------------------------------------------------------------------
// GEMM 1 (tf32 mma, cp.async 2-stage pipeline): qkv = x @ W_qkv + b_qkv
// ---------------------------------------------------------------------------
__global__ __launch_bounds__(256, 2) void gemm_qkv_tc(
    const float* __restrict__ X, const float* __restrict__ W,
    const float* __restrict__ bias)
{
    constexpr int K = DD;
    constexpr int N = 3 * DD;
    extern __shared__ float smem[];
    float* As = smem;                  // [2][128][36]
    float* Bs = smem + 2 * 128 * 36;   // [2][32][136]

    const int tid = threadIdx.x;
    const int lane = tid & 31;
    const int wid = tid >> 5;
    const int wm = wid >> 1;
    const int wn = wid & 1;
    const int mtile = blockIdx.y * 128;
    const int ntile = blockIdx.x * 128;

    float c[2][8][4];
#pragma unroll
    for (int mt = 0; mt < 2; ++mt)
#pragma unroll
        for (int nt = 0; nt < 8; ++nt)
#pragma unroll
            for (int i = 0; i < 4; ++i) c[mt][nt][i] = 0.f;

    const int lm = tid >> 3;
    const int lj = tid & 7;
    const int bkr = tid >> 5;
    const int bnj = tid & 31;
    const int gr = lane >> 2;
    const int gc = lane & 3;

    auto load_stage = [&](int s, int k0) {
#pragma unroll
        for (int it = 0; it < 4; ++it) {
            const int m = lm + 32 * it;
            cp_async16(&As[(s * 128 + m) * 36 + 4 * lj],
                       X + (size_t)(mtile + m) * K + k0 + 4 * lj);
        }
#pragma unroll
        for (int it = 0; it < 4; ++it) {
            const int kr = bkr + 8 * it;
            cp_async16(&Bs[(s * 32 + kr) * 136 + 4 * bnj],
                       W + (size_t)(k0 + kr) * N + ntile + 4 * bnj);
        }
        CP_COMMIT();
    };

    constexpr int NIT = K / 32;   // 32
    load_stage(0, 0);

    for (int i = 0; i < NIT; ++i) {
        const int s = i & 1;
        if (i + 1 < NIT) {
            load_stage((i + 1) & 1, (i + 1) * 32);
            CP_WAIT(1);
        } else {
            CP_WAIT(0);
        }
        __syncthreads();

        const float* Asb = As + s * 128 * 36;
        const float* Bsb = Bs + s * 32 * 136;
#pragma unroll
        for (int ks = 0; ks < 4; ++ks) {
            const int kk = ks * 8;
            uint32_t a[2][4];
#pragma unroll
            for (int mt = 0; mt < 2; ++mt) {
                const int r = wm * 32 + mt * 16 + gr;
                a[mt][0] = tf32_bits(Asb[r * 36 + kk + gc]);
                a[mt][1] = tf32_bits(Asb[(r + 8) * 36 + kk + gc]);
                a[mt][2] = tf32_bits(Asb[r * 36 + kk + gc + 4]);
                a[mt][3] = tf32_bits(Asb[(r + 8) * 36 + kk + gc + 4]);
            }
            uint32_t b[8][2];
#pragma unroll
            for (int nt = 0; nt < 8; ++nt) {
                const int n = wn * 64 + nt * 8 + gr;
                b[nt][0] = tf32_bits(Bsb[(kk + gc) * 136 + n]);
                b[nt][1] = tf32_bits(Bsb[(kk + gc + 4) * 136 + n]);
            }
#pragma unroll
            for (int mt = 0; mt < 2; ++mt)
#pragma unroll
                for (int nt = 0; nt < 8; ++nt)
                    mma_tf32(c[mt][nt], a[mt], b[nt]);
        }
        __syncthreads();
    }

    // epilogue: bias + scatter to q/k/v [b,h,t,hd]
#pragma unroll
    for (int mt = 0; mt < 2; ++mt) {
        const int r0 = mtile + wm * 32 + mt * 16 + gr;
#pragma unroll
        for (int nt = 0; nt < 8; ++nt) {
            const int col = ntile + wn * 64 + nt * 8 + gc * 2;
            const float bz0 = bias[col], bz1 = bias[col + 1];
            const int which = col >> 10;
            const int dcol = col & 1023;
            const int h_ = dcol >> 6, hd_ = dcol & 63;
            float* dst = (which == 0) ? g_q : (which == 1) ? g_k : g_v;
#pragma unroll
            for (int half = 0; half < 2; ++half) {
                const int row = r0 + half * 8;
                const int b_ = row >> 11, t_ = row & 2047;
                float2 v = make_float2(c[mt][nt][2 * half + 0] + bz0,
                                       c[mt][nt][2 * half + 1] + bz1);
                *(float2*)&dst[(((size_t)b_ * HH + h_) * TT + t_) * HD + hd_] = v;
            }
        }
    }
}

// ---------------------------------------------------------------------------
// Flash attention (causal) on tensor cores (tf32 mma), cp.async 2-stage K/V.
// 256 threads = 8 warps; warp owns 16 q-rows x full KV tile (64 keys).
// K smem stride 68, V smem stride 72 -> conflict-free B-fragment LDS.
// ---------------------------------------------------------------------------
#define BKV 64
#define KSTR 68
#define VSTR 72
#define ATTN_SMEM_FLOATS (2*BKV*KSTR + 2*BKV*VSTR)
#define ATTN_SMEM_BYTES  (ATTN_SMEM_FLOATS * 4)

__global__ __launch_bounds__(256) void attn_tc_kernel()
{
    const int bh = blockIdx.y;
    const int qtile = blockIdx.x;
    const int tid = threadIdx.x;
    const int lane = tid & 31;
    const int warp = tid >> 5;
    const int gr = lane >> 2;
    const int gc = lane & 3;

    const int qbase = qtile * 128;
    const int row0 = qbase + warp * 16 + gr;

    const float* Qb = g_q + (size_t)bh * TT * HD;
    const float* Kb = g_k + (size_t)bh * TT * HD;
    const float* Vb = g_v + (size_t)bh * TT * HD;

    extern __shared__ float smem[];
    float* Ks = smem;                 // [2][BKV][KSTR]
    float* Vs = smem + 2 * BKV * KSTR; // [2][BKV][VSTR]

    const float QSCALE = 0.125f * 1.4426950408889634f;
    uint32_t qf[8][4];
#pragma unroll
    for (int ks = 0; ks < 8; ++ks) {
        const int kk = ks * 8;
        qf[ks][0] = tf32_bits(Qb[(size_t)row0 * HD + kk + gc] * QSCALE);
        qf[ks][1] = tf32_bits(Qb[(size_t)(row0 + 8) * HD + kk + gc] * QSCALE);
        qf[ks][2] = tf32_bits(Qb[(size_t)row0 * HD + kk + gc + 4] * QSCALE);
        qf[ks][3] = tf32_bits(Qb[(size_t)(row0 + 8) * HD + kk + gc + 4] * QSCALE);
    }

    float o[8][4];
#pragma unroll
    for (int nt = 0; nt < 8; ++nt)
#pragma unroll
        for (int i = 0; i < 4; ++i) o[nt][i] = 0.f;
    float m0 = -1e30f, m1 = -1e30f;
    float l0 = 0.f, l1 = 0.f;

    // K/V tile loader: 64 rows x 16 float4 per tensor = 1024 float4; 4/thread.
    auto load_kv = [&](int s, int k0) {
#pragma unroll
        for (int it = 0; it < 4; ++it) {
            const int c = tid + 256 * it;
            const int row = c >> 4;
            const int c4 = (c & 15) * 4;
            cp_async16(&Ks[(s * BKV + row) * KSTR + c4],
                       Kb + (size_t)(k0 + row) * HD + c4);
            cp_async16(&Vs[(s * BKV + row) * VSTR + c4],
                       Vb + (size_t)(k0 + row) * HD + c4);
        }
        CP_COMMIT();
    };

    const int ntiles = (qbase + 128) / BKV;   // 2*(qtile+1)
    load_kv(0, 0);

    for (int t = 0; t < ntiles; ++t) {
        const int s = t & 1;
        const int k0 = t * BKV;
        if (t + 1 < ntiles) {
            load_kv((t + 1) & 1, (t + 1) * BKV);
            CP_WAIT(1);
        } else {
            CP_WAIT(0);
        }
        __syncthreads();

        const float* Ksb = Ks + s * BKV * KSTR;
        const float* Vsb = Vs + s * BKV * VSTR;

        float sc[8][4];
#pragma unroll
        for (int nt = 0; nt < 8; ++nt)
#pragma unroll
            for (int i = 0; i < 4; ++i) sc[nt][i] = 0.f;
#pragma unroll
        for (int ks = 0; ks < 8; ++ks) {
            const int kk = ks * 8;
#pragma unroll
            for (int nt = 0; nt < 8; ++nt) {
                uint32_t b[2];
                b[0] = tf32_bits(Ksb[(nt * 8 + gr) * KSTR + kk + gc]);
                b[1] = tf32_bits(Ksb[(nt * 8 + gr) * KSTR + kk + gc + 4]);
                mma_tf32(sc[nt], qf[ks], b);
            }
        }

        if (k0 + BKV > qbase) {
#pragma unroll
            for (int nt = 0; nt < 8; ++nt) {
                const int col = k0 + nt * 8 + 2 * gc;
                if (col > row0)           sc[nt][0] = -1e30f;
                if (col + 1 > row0)       sc[nt][1] = -1e30f;
                if (col > row0 + 8)       sc[nt][2] = -1e30f;
                if (col + 1 > row0 + 8)   sc[nt][3] = -1e30f;
            }
        }

        float t0 = -1e30f, t1 = -1e30f;
#pragma unroll
        for (int nt = 0; nt < 8; ++nt) {
            t0 = fmaxf(t0, fmaxf(sc[nt][0], sc[nt][1]));
            t1 = fmaxf(t1, fmaxf(sc[nt][2], sc[nt][3]));
        }
        t0 = fmaxf(t0, __shfl_xor_sync(0xffffffffu, t0, 1));
        t0 = fmaxf(t0, __shfl_xor_sync(0xffffffffu, t0, 2));
        t1 = fmaxf(t1, __shfl_xor_sync(0xffffffffu, t1, 1));
        t1 = fmaxf(t1, __shfl_xor_sync(0xffffffffu, t1, 2));

        const float mn0 = fmaxf(m0, t0);
        const float mn1 = fmaxf(m1, t1);
        const float c0 = ex2(m0 - mn0);
        const float c1 = ex2(m1 - mn1);
        m0 = mn0; m1 = mn1;
        l0 *= c0; l1 *= c1;
#pragma unroll
        for (int nt = 0; nt < 8; ++nt) {
            o[nt][0] *= c0; o[nt][1] *= c0;
            o[nt][2] *= c1; o[nt][3] *= c1;
        }

        uint32_t p[8][4];
#pragma unroll
        for (int nt = 0; nt < 8; ++nt) {
            float p0 = ex2(sc[nt][0] - mn0);
            float p1 = ex2(sc[nt][1] - mn0);
            float p2 = ex2(sc[nt][2] - mn1);
            float p3 = ex2(sc[nt][3] - mn1);
            l0 += p0 + p1;
            l1 += p2 + p3;
            p[nt][0] = tf32_bits(p0);
            p[nt][1] = tf32_bits(p1);
            p[nt][2] = tf32_bits(p2);
            p[nt][3] = tf32_bits(p3);
        }

        const int L1 = (lane & ~3) | (gc >> 1);
        const int L2 = L1 + 2;
        const bool hi = (gc & 1);
#pragma unroll
        for (int ks = 0; ks < 8; ++ks) {
            uint32_t a[4];
            {
                uint32_t x0 = __shfl_sync(0xffffffffu, p[ks][0], L1);
                uint32_t x1 = __shfl_sync(0xffffffffu, p[ks][1], L1);
                uint32_t x2 = __shfl_sync(0xffffffffu, p[ks][2], L1);
                uint32_t x3 = __shfl_sync(0xffffffffu, p[ks][3], L1);
                a[0] = hi ? x1 : x0;
                a[1] = hi ? x3 : x2;
                uint32_t y0 = __shfl_sync(0xffffffffu, p[ks][0], L2);
                uint32_t y1 = __shfl_sync(0xffffffffu, p[ks][1], L2);
                uint32_t y2 = __shfl_sync(0xffffffffu, p[ks][2], L2);
                uint32_t y3 = __shfl_sync(0xffffffffu, p[ks][3], L2);
                a[2] = hi ? y1 : y0;
                a[3] = hi ? y3 : y2;
            }
            const int kk = ks * 8;
#pragma unroll
            for (int nt = 0; nt < 8; ++nt) {
                uint32_t b[2];
                b[0] = tf32_bits(Vsb[(kk + gc) * VSTR + nt * 8 + gr]);
                b[1] = tf32_bits(Vsb[(kk + gc + 4) * VSTR + nt * 8 + gr]);
                mma_tf32(o[nt], a, b);
            }
        }
        __syncthreads();
    }

    l0 += __shfl_xor_sync(0xffffffffu, l0, 1);
    l0 += __shfl_xor_sync(0xffffffffu, l0, 2);
    l1 += __shfl_xor_sync(0xffffffffu, l1, 1);
    l1 += __shfl_xor_sync(0xffffffffu, l1, 2);
    const float inv0 = 1.0f / l0;
    const float inv1 = 1.0f / l1;

    const int b_ = bh >> 4, h_ = bh & 15;
#pragma unroll
    for (int nt = 0; nt < 8; ++nt) {
        const int col = nt * 8 + 2 * gc;
        float2 v0 = make_float2(o[nt][0] * inv0, o[nt][1] * inv0);
        float2 v1 = make_float2(o[nt][2] * inv1, o[nt][3] * inv1);
        *(float2*)&g_attn[(((size_t)b_ * TT + row0) * HH + h_) * HD + col] = v0;
        *(float2*)&g_attn[(((size_t)b_ * TT + row0 + 8) * HH + h_) * HD + col] = v1;
    }
}

// ---------------------------------------------------------------------------
// GEMM 2 (tf32 mma, cp.async 2-stage pipeline): out = attn @ W_out + b_out
// ---------------------------------------------------------------------------
__global__ __launch_bounds__(256, 2) void gemm_out_tc(
    const float* __restrict__ W, const float* __restrict__ bias,
    float* __restrict__ Out)
{
    constexpr int K = DD;
    constexpr int N = DD;
    extern __shared__ float smem[];
    float* As = smem;
    float* Bs = smem + 2 * 128 * 36;

    const int tid = threadIdx.x;
    const int lane = tid & 31;
    const int wid = tid >> 5;
    const int wm = wid >> 1;
    const int wn = wid & 1;
    const int mtile = blockIdx.y * 128;
    const int ntile = blockIdx.x * 128;

    float c[2][8][4];
#pragma unroll
    for (int mt = 0; mt < 2; ++mt)
#pragma unroll
        for (int nt = 0; nt < 8; ++nt)
#pragma unroll
            for (int i = 0; i < 4; ++i) c[mt][nt][i] = 0.f;

    const int lm = tid >> 3;
    const int lj = tid & 7;
    const int bkr = tid >> 5;
    const int bnj = tid & 31;
    const int gr = lane >> 2;
    const int gc = lane & 3;

    auto load_stage = [&](int s, int k0) {
#pragma unroll
        for (int it = 0; it < 4; ++it) {
            const int m = lm + 32 * it;
            cp_async16(&As[(s * 128 + m) * 36 + 4 * lj],
                       g_attn + (size_t)(mtile + m) * K + k0 + 4 * lj);
        }
#pragma unroll
        for (int it = 0; it < 4; ++it) {
            const int kr = bkr + 8 * it;
            cp_async16(&Bs[(s * 32 + kr) * 136 + 4 * bnj],
                       W + (size_t)(k0 + kr) * N + ntile + 4 * bnj);
        }
        CP_COMMIT();
    };

    constexpr int NIT = K / 32;
    load_stage(0, 0);

    for (int i = 0; i < NIT; ++i) {
        const int s = i & 1;
        if (i + 1 < NIT) {
            load_stage((i + 1) & 1, (i + 1) * 32);
            CP_WAIT(1);
        } else {
            CP_WAIT(0);
        }
        __syncthreads();

        const float* Asb = As + s * 128 * 36;
        const float* Bsb = Bs + s * 32 * 136;
#pragma unroll
        for (int ks = 0; ks < 4; ++ks) {
            const int kk = ks * 8;
            uint32_t a[2][4];
#pragma unroll
            for (int mt = 0; mt < 2; ++mt) {
                const int r = wm * 32 + mt * 16 + gr;
                a[mt][0] = tf32_bits(Asb[r * 36 + kk + gc]);
                a[mt][1] = tf32_bits(Asb[(r + 8) * 36 + kk + gc]);
                a[mt][2] = tf32_bits(Asb[r * 36 + kk + gc + 4]);
                a[mt][3] = tf32_bits(Asb[(r + 8) * 36 + kk + gc + 4]);
            }
            uint32_t b[8][2];
#pragma unroll
            for (int nt = 0; nt < 8; ++nt) {
                const int n = wn * 64 + nt * 8 + gr;
                b[nt][0] = tf32_bits(Bsb[(kk + gc) * 136 + n]);
                b[nt][1] = tf32_bits(Bsb[(kk + gc + 4) * 136 + n]);
            }
#pragma unroll
            for (int mt = 0; mt < 2; ++mt)
#pragma unroll
                for (int nt = 0; nt < 8; ++nt)
                    mma_tf32(c[mt][nt], a[mt], b[nt]);
        }
        __syncthreads();
    }

#pragma unroll
    for (int mt = 0; mt < 2; ++mt) {
        const int r0 = mtile + wm * 32 + mt * 16 + gr;
#pragma unroll
        for (int nt = 0; nt < 8; ++nt) {
            const int col = ntile + wn * 64 + nt * 8 + gc * 2;
            const float bz0 = bias[col], bz1 = bias[col + 1];
#pragma unroll
            for (int half = 0; half < 2; ++half) {
                const int row = r0 + half * 8;
                float2 v = make_float2(c[mt][nt][2 * half + 0] + bz0,
                                       c[mt][nt][2 * half + 1] + bz1);
                *(float2*)&Out[(size_t)row * N + col] = v;
            }
        }
    }
}

// ---------------------------------------------------------------------------
extern "C" void kernel_launch(void* const* d_in, const int* in_sizes, int n_in,
                              void* d_out, int out_size)
{
    const float* x     = (const float*)d_in[0];
    const float* W_qkv = (const float*)d_in[1];
    const float* b_qkv = (const float*)d_in[2];
    const float* W_out = (const float*)d_in[3];
    const float* b_out = (const float*)d_in[4];
    float* out = (float*)d_out;

    cudaFuncSetAttribute(gemm_qkv_tc, cudaFuncAttributeMaxDynamicSharedMemorySize,
                         GEMM_SMEM_BYTES);
    cudaFuncSetAttribute(attn_tc_kernel, cudaFuncAttributeMaxDynamicSharedMemorySize,
                         ATTN_SMEM_BYTES);
    cudaFuncSetAttribute(gemm_out_tc, cudaFuncAttributeMaxDynamicSharedMemorySize,
                         GEMM_SMEM_BYTES);

    {
        dim3 grid(3 * DD / 128, MROWS / 128);   // (24, 64)
        gemm_qkv_tc<<<grid, 256, GEMM_SMEM_BYTES>>>(x, W_qkv, b_qkv);
    }
    {
        dim3 grid(TT / 128, BB * HH);           // (16, 64)
        attn_tc_kernel<<<grid, 256, ATTN_SMEM_BYTES>>>();
    }
    {
        dim3 grid(DD / 128, MROWS / 128);       // (8, 64)
        gemm_out_tc<<<grid, 256, GEMM_SMEM_BYTES>>>(W_out, b_out, out);
    }
}

// round 15
// speedup vs baseline: 7.0153x; 1.0156x over previous
#include <cuda_runtime.h>
#include <cstdint>

#define BB 4
#define TT 2048
#define DD 1024
#define HH 16
#define HD 64
#define MROWS (BB*TT)   // 8192

// scratch
__device__ float g_q[BB*HH*TT*HD];     // [b,h,t,hd]  (tf32-rounded values)
__device__ float g_k[BB*HH*TT*HD];     // [b,h,t,hd]  (tf32-rounded values)
__device__ float g_v[BB*HH*TT*HD];     // [b,h,t,hd]  (tf32-rounded values)
__device__ float g_attn[BB*TT*DD];     // [b,t,h,hd]  (tf32-rounded values)
__device__ float g_xr[MROWS*DD];       // tf32-rounded X
__device__ float g_wqkvr[DD*3*DD];     // tf32-rounded W_qkv
__device__ float g_woutr[DD*DD];       // tf32-rounded W_out

// ---------------------------------------------------------------------------
// helpers
// ---------------------------------------------------------------------------
__device__ __forceinline__ float to_tf32(float x) {
    uint32_t r;
    asm("cvt.rna.tf32.f32 %0, %1;" : "=r"(r) : "f"(x));
    return __uint_as_float(r);
}
__device__ __forceinline__ uint32_t tf32_bits(float x) {
    uint32_t r;
    asm("cvt.rna.tf32.f32 %0, %1;" : "=r"(r) : "f"(x));
    return r;
}
__device__ __forceinline__ float ex2(float x) {
    float r;
    asm("ex2.approx.f32 %0, %1;" : "=f"(r) : "f"(x));
    return r;
}
__device__ __forceinline__ void mma_tf32(float* c, const uint32_t* a, const uint32_t* b) {
    asm volatile(
        "mma.sync.aligned.m16n8k8.row.col.f32.tf32.tf32.f32 "
        "{%0,%1,%2,%3}, {%4,%5,%6,%7}, {%8,%9}, {%0,%1,%2,%3};"
        : "+f"(c[0]), "+f"(c[1]), "+f"(c[2]), "+f"(c[3])
        : "r"(a[0]), "r"(a[1]), "r"(a[2]), "r"(a[3]), "r"(b[0]), "r"(b[1]));
}
__device__ __forceinline__ void cp_async16(void* smem_dst, const void* gsrc) {
    uint32_t sa = (uint32_t)__cvta_generic_to_shared(smem_dst);
    asm volatile("cp.async.cg.shared.global [%0], [%1], 16;" :: "r"(sa), "l"(gsrc));
}
#define CP_COMMIT()  asm volatile("cp.async.commit_group;")
#define CP_WAIT(n)   asm volatile("cp.async.wait_group %0;" :: "n"(n))

// Pre-pass: elementwise tf32 rounding (float4-vectorized)
__global__ __launch_bounds__(256) void round_tf32_kernel(
    const float* __restrict__ src, float* __restrict__ dst, int n4)
{
    const int i = blockIdx.x * blockDim.x + threadIdx.x;
    if (i < n4) {
        float4 v = ((const float4*)src)[i];
        ((float4*)dst)[i] = make_float4(to_tf32(v.x), to_tf32(v.y),
                                        to_tf32(v.z), to_tf32(v.w));
    }
}

// Pipelined GEMM smem: [2][128][36] A + [2][32][136] B (floats)
#define GEMM_SMEM_FLOATS (2*128*36 + 2*32*136)
#define GEMM_SMEM_BYTES  (GEMM_SMEM_FLOATS * 4)

// ---------------------------------------------------------------------------
// GEMM 1 (tf32 mma, cp.async 2-stage, pre-rounded operands): qkv projection
// ---------------------------------------------------------------------------
__global__ __launch_bounds__(256, 2) void gemm_qkv_tc(
    const float* __restrict__ bias)
{
    constexpr int K = DD;
    constexpr int N = 3 * DD;
    extern __shared__ float smem[];
    float* As = smem;                  // [2][128][36]
    float* Bs = smem + 2 * 128 * 36;   // [2][32][136]

    const int tid = threadIdx.x;
    const int lane = tid & 31;
    const int wid = tid >> 5;
    const int wm = wid >> 1;
    const int wn = wid & 1;
    const int mtile = blockIdx.y * 128;
    const int ntile = blockIdx.x * 128;

    float c[2][8][4];
#pragma unroll
    for (int mt = 0; mt < 2; ++mt)
#pragma unroll
        for (int nt = 0; nt < 8; ++nt)
#pragma unroll
            for (int i = 0; i < 4; ++i) c[mt][nt][i] = 0.f;

    const int lm = tid >> 3;
    const int lj = tid & 7;
    const int bkr = tid >> 5;
    const int bnj = tid & 31;
    const int gr = lane >> 2;
    const int gc = lane & 3;

    auto load_stage = [&](int s, int k0) {
#pragma unroll
        for (int it = 0; it < 4; ++it) {
            const int m = lm + 32 * it;
            cp_async16(&As[(s * 128 + m) * 36 + 4 * lj],
                       g_xr + (size_t)(mtile + m) * K + k0 + 4 * lj);
        }
#pragma unroll
        for (int it = 0; it < 4; ++it) {
            const int kr = bkr + 8 * it;
            cp_async16(&Bs[(s * 32 + kr) * 136 + 4 * bnj],
                       g_wqkvr + (size_t)(k0 + kr) * N + ntile + 4 * bnj);
        }
        CP_COMMIT();
    };

    constexpr int NIT = K / 32;   // 32
    load_stage(0, 0);

    for (int i = 0; i < NIT; ++i) {
        const int s = i & 1;
        if (i + 1 < NIT) {
            load_stage((i + 1) & 1, (i + 1) * 32);
            CP_WAIT(1);
        } else {
            CP_WAIT(0);
        }
        __syncthreads();

        const float* Asb = As + s * 128 * 36;
        const float* Bsb = Bs + s * 32 * 136;
#pragma unroll
        for (int ks = 0; ks < 4; ++ks) {
            const int kk = ks * 8;
            uint32_t a[2][4];
#pragma unroll
            for (int mt = 0; mt < 2; ++mt) {
                const int r = wm * 32 + mt * 16 + gr;
                a[mt][0] = __float_as_uint(Asb[r * 36 + kk + gc]);
                a[mt][1] = __float_as_uint(Asb[(r + 8) * 36 + kk + gc]);
                a[mt][2] = __float_as_uint(Asb[r * 36 + kk + gc + 4]);
                a[mt][3] = __float_as_uint(Asb[(r + 8) * 36 + kk + gc + 4]);
            }
            uint32_t b[8][2];
#pragma unroll
            for (int nt = 0; nt < 8; ++nt) {
                const int n = wn * 64 + nt * 8 + gr;
                b[nt][0] = __float_as_uint(Bsb[(kk + gc) * 136 + n]);
                b[nt][1] = __float_as_uint(Bsb[(kk + gc + 4) * 136 + n]);
            }
#pragma unroll
            for (int mt = 0; mt < 2; ++mt)
#pragma unroll
                for (int nt = 0; nt < 8; ++nt)
                    mma_tf32(c[mt][nt], a[mt], b[nt]);
        }
        __syncthreads();
    }

    // epilogue: bias + tf32-round + scatter to q/k/v [b,h,t,hd]
#pragma unroll
    for (int mt = 0; mt < 2; ++mt) {
        const int r0 = mtile + wm * 32 + mt * 16 + gr;
#pragma unroll
        for (int nt = 0; nt < 8; ++nt) {
            const int col = ntile + wn * 64 + nt * 8 + gc * 2;
            const float bz0 = bias[col], bz1 = bias[col + 1];
            const int which = col >> 10;
            const int dcol = col & 1023;
            const int h_ = dcol >> 6, hd_ = dcol & 63;
            float* dst = (which == 0) ? g_q : (which == 1) ? g_k : g_v;
#pragma unroll
            for (int half = 0; half < 2; ++half) {
                const int row = r0 + half * 8;
                const int b_ = row >> 11, t_ = row & 2047;
                float2 v = make_float2(to_tf32(c[mt][nt][2 * half + 0] + bz0),
                                       to_tf32(c[mt][nt][2 * half + 1] + bz1));
                *(float2*)&dst[(((size_t)b_ * HH + h_) * TT + t_) * HD + hd_] = v;
            }
        }
    }
}

// ---------------------------------------------------------------------------
// Flash attention (causal) on tensor cores, cp.async 2-stage K/V, raw tf32.
// ---------------------------------------------------------------------------
#define BKV 64
#define KSTR 68
#define VSTR 72
#define ATTN_SMEM_FLOATS (2*BKV*KSTR + 2*BKV*VSTR)
#define ATTN_SMEM_BYTES  (ATTN_SMEM_FLOATS * 4)

__global__ __launch_bounds__(256) void attn_tc_kernel()
{
    const int bh = blockIdx.y;
    const int qtile = blockIdx.x;
    const int tid = threadIdx.x;
    const int lane = tid & 31;
    const int warp = tid >> 5;
    const int gr = lane >> 2;
    const int gc = lane & 3;

    const int qbase = qtile * 128;
    const int row0 = qbase + warp * 16 + gr;

    const float* Qb = g_q + (size_t)bh * TT * HD;
    const float* Kb = g_k + (size_t)bh * TT * HD;
    const float* Vb = g_v + (size_t)bh * TT * HD;

    extern __shared__ float smem[];
    float* Ks = smem;                  // [2][BKV][KSTR]
    float* Vs = smem + 2 * BKV * KSTR; // [2][BKV][VSTR]

    const float QSCALE = 0.125f * 1.4426950408889634f;
    uint32_t qf[8][4];
#pragma unroll
    for (int ks = 0; ks < 8; ++ks) {
        const int kk = ks * 8;
        qf[ks][0] = tf32_bits(Qb[(size_t)row0 * HD + kk + gc] * QSCALE);
        qf[ks][1] = tf32_bits(Qb[(size_t)(row0 + 8) * HD + kk + gc] * QSCALE);
        qf[ks][2] = tf32_bits(Qb[(size_t)row0 * HD + kk + gc + 4] * QSCALE);
        qf[ks][3] = tf32_bits(Qb[(size_t)(row0 + 8) * HD + kk + gc + 4] * QSCALE);
    }

    float o[8][4];
#pragma unroll
    for (int nt = 0; nt < 8; ++nt)
#pragma unroll
        for (int i = 0; i < 4; ++i) o[nt][i] = 0.f;
    float m0 = -1e30f, m1 = -1e30f;
    float l0 = 0.f, l1 = 0.f;

    auto load_kv = [&](int s, int k0) {
#pragma unroll
        for (int it = 0; it < 4; ++it) {
            const int c = tid + 256 * it;
            const int row = c >> 4;
            const int c4 = (c & 15) * 4;
            cp_async16(&Ks[(s * BKV + row) * KSTR + c4],
                       Kb + (size_t)(k0 + row) * HD + c4);
            cp_async16(&Vs[(s * BKV + row) * VSTR + c4],
                       Vb + (size_t)(k0 + row) * HD + c4);
        }
        CP_COMMIT();
    };

    const int ntiles = (qbase + 128) / BKV;
    load_kv(0, 0);

    for (int t = 0; t < ntiles; ++t) {
        const int s = t & 1;
        const int k0 = t * BKV;
        if (t + 1 < ntiles) {
            load_kv((t + 1) & 1, (t + 1) * BKV);
            CP_WAIT(1);
        } else {
            CP_WAIT(0);
        }
        __syncthreads();

        const float* Ksb = Ks + s * BKV * KSTR;
        const float* Vsb = Vs + s * BKV * VSTR;

        float sc[8][4];
#pragma unroll
        for (int nt = 0; nt < 8; ++nt)
#pragma unroll
            for (int i = 0; i < 4; ++i) sc[nt][i] = 0.f;
#pragma unroll
        for (int ks = 0; ks < 8; ++ks) {
            const int kk = ks * 8;
#pragma unroll
            for (int nt = 0; nt < 8; ++nt) {
                uint32_t b[2];
                b[0] = __float_as_uint(Ksb[(nt * 8 + gr) * KSTR + kk + gc]);
                b[1] = __float_as_uint(Ksb[(nt * 8 + gr) * KSTR + kk + gc + 4]);
                mma_tf32(sc[nt], qf[ks], b);
            }
        }

        if (k0 + BKV > qbase) {
#pragma unroll
            for (int nt = 0; nt < 8; ++nt) {
                const int col = k0 + nt * 8 + 2 * gc;
                if (col > row0)           sc[nt][0] = -1e30f;
                if (col + 1 > row0)       sc[nt][1] = -1e30f;
                if (col > row0 + 8)       sc[nt][2] = -1e30f;
                if (col + 1 > row0 + 8)   sc[nt][3] = -1e30f;
            }
        }

        float t0 = -1e30f, t1 = -1e30f;
#pragma unroll
        for (int nt = 0; nt < 8; ++nt) {
            t0 = fmaxf(t0, fmaxf(sc[nt][0], sc[nt][1]));
            t1 = fmaxf(t1, fmaxf(sc[nt][2], sc[nt][3]));
        }
        t0 = fmaxf(t0, __shfl_xor_sync(0xffffffffu, t0, 1));
        t0 = fmaxf(t0, __shfl_xor_sync(0xffffffffu, t0, 2));
        t1 = fmaxf(t1, __shfl_xor_sync(0xffffffffu, t1, 1));
        t1 = fmaxf(t1, __shfl_xor_sync(0xffffffffu, t1, 2));

        const float mn0 = fmaxf(m0, t0);
        const float mn1 = fmaxf(m1, t1);
        const float c0 = ex2(m0 - mn0);
        const float c1 = ex2(m1 - mn1);
        m0 = mn0; m1 = mn1;
        l0 *= c0; l1 *= c1;
#pragma unroll
        for (int nt = 0; nt < 8; ++nt) {
            o[nt][0] *= c0; o[nt][1] *= c0;
            o[nt][2] *= c1; o[nt][3] *= c1;
        }

        uint32_t p[8][4];
#pragma unroll
        for (int nt = 0; nt < 8; ++nt) {
            float p0 = ex2(sc[nt][0] - mn0);
            float p1 = ex2(sc[nt][1] - mn0);
            float p2 = ex2(sc[nt][2] - mn1);
            float p3 = ex2(sc[nt][3] - mn1);
            l0 += p0 + p1;
            l1 += p2 + p3;
            p[nt][0] = tf32_bits(p0);
            p[nt][1] = tf32_bits(p1);
            p[nt][2] = tf32_bits(p2);
            p[nt][3] = tf32_bits(p3);
        }

        const int L1 = (lane & ~3) | (gc >> 1);
        const int L2 = L1 + 2;
        const bool hi = (gc & 1);
#pragma unroll
        for (int ks = 0; ks < 8; ++ks) {
            uint32_t a[4];
            {
                uint32_t x0 = __shfl_sync(0xffffffffu, p[ks][0], L1);
                uint32_t x1 = __shfl_sync(0xffffffffu, p[ks][1], L1);
                uint32_t x2 = __shfl_sync(0xffffffffu, p[ks][2], L1);
                uint32_t x3 = __shfl_sync(0xffffffffu, p[ks][3], L1);
                a[0] = hi ? x1 : x0;
                a[1] = hi ? x3 : x2;
                uint32_t y0 = __shfl_sync(0xffffffffu, p[ks][0], L2);
                uint32_t y1 = __shfl_sync(0xffffffffu, p[ks][1], L2);
                uint32_t y2 = __shfl_sync(0xffffffffu, p[ks][2], L2);
                uint32_t y3 = __shfl_sync(0xffffffffu, p[ks][3], L2);
                a[2] = hi ? y1 : y0;
                a[3] = hi ? y3 : y2;
            }
            const int kk = ks * 8;
#pragma unroll
            for (int nt = 0; nt < 8; ++nt) {
                uint32_t b[2];
                b[0] = __float_as_uint(Vsb[(kk + gc) * VSTR + nt * 8 + gr]);
                b[1] = __float_as_uint(Vsb[(kk + gc + 4) * VSTR + nt * 8 + gr]);
                mma_tf32(o[nt], a, b);
            }
        }
        __syncthreads();
    }

    l0 += __shfl_xor_sync(0xffffffffu, l0, 1);
    l0 += __shfl_xor_sync(0xffffffffu, l0, 2);
    l1 += __shfl_xor_sync(0xffffffffu, l1, 1);
    l1 += __shfl_xor_sync(0xffffffffu, l1, 2);
    const float inv0 = 1.0f / l0;
    const float inv1 = 1.0f / l1;

    const int b_ = bh >> 4, h_ = bh & 15;
#pragma unroll
    for (int nt = 0; nt < 8; ++nt) {
        const int col = nt * 8 + 2 * gc;
        float2 v0 = make_float2(to_tf32(o[nt][0] * inv0), to_tf32(o[nt][1] * inv0));
        float2 v1 = make_float2(to_tf32(o[nt][2] * inv1), to_tf32(o[nt][3] * inv1));
        *(float2*)&g_attn[(((size_t)b_ * TT + row0) * HH + h_) * HD + col] = v0;
        *(float2*)&g_attn[(((size_t)b_ * TT + row0 + 8) * HH + h_) * HD + col] = v1;
    }
}

// ---------------------------------------------------------------------------
// GEMM 2 (tf32 mma, cp.async 2-stage, pre-rounded operands): out projection
// ---------------------------------------------------------------------------
__global__ __launch_bounds__(256, 2) void gemm_out_tc(
    const float* __restrict__ bias, float* __restrict__ Out)
{
    constexpr int K = DD;
    constexpr int N = DD;
    extern __shared__ float smem[];
    float* As = smem;
    float* Bs = smem + 2 * 128 * 36;

    const int tid = threadIdx.x;
    const int lane = tid & 31;
    const int wid = tid >> 5;
    const int wm = wid >> 1;
    const int wn = wid & 1;
    const int mtile = blockIdx.y * 128;
    const int ntile = blockIdx.x * 128;

    float c[2][8][4];
#pragma unroll
    for (int mt = 0; mt < 2; ++mt)
#pragma unroll
        for (int nt = 0; nt < 8; ++nt)
#pragma unroll
            for (int i = 0; i < 4; ++i) c[mt][nt][i] = 0.f;

    const int lm = tid >> 3;
    const int lj = tid & 7;
    const int bkr = tid >> 5;
    const int bnj = tid & 31;
    const int gr = lane >> 2;
    const int gc = lane & 3;

    auto load_stage = [&](int s, int k0) {
#pragma unroll
        for (int it = 0; it < 4; ++it) {
            const int m = lm + 32 * it;
            cp_async16(&As[(s * 128 + m) * 36 + 4 * lj],
                       g_attn + (size_t)(mtile + m) * K + k0 + 4 * lj);
        }
#pragma unroll
        for (int it = 0; it < 4; ++it) {
            const int kr = bkr + 8 * it;
            cp_async16(&Bs[(s * 32 + kr) * 136 + 4 * bnj],
                       g_woutr + (size_t)(k0 + kr) * N + ntile + 4 * bnj);
        }
        CP_COMMIT();
    };

    constexpr int NIT = K / 32;
    load_stage(0, 0);

    for (int i = 0; i < NIT; ++i) {
        const int s = i & 1;
        if (i + 1 < NIT) {
            load_stage((i + 1) & 1, (i + 1) * 32);
            CP_WAIT(1);
        } else {
            CP_WAIT(0);
        }
        __syncthreads();

        const float* Asb = As + s * 128 * 36;
        const float* Bsb = Bs + s * 32 * 136;
#pragma unroll
        for (int ks = 0; ks < 4; ++ks) {
            const int kk = ks * 8;
            uint32_t a[2][4];
#pragma unroll
            for (int mt = 0; mt < 2; ++mt) {
                const int r = wm * 32 + mt * 16 + gr;
                a[mt][0] = __float_as_uint(Asb[r * 36 + kk + gc]);
                a[mt][1] = __float_as_uint(Asb[(r + 8) * 36 + kk + gc]);
                a[mt][2] = __float_as_uint(Asb[r * 36 + kk + gc + 4]);
                a[mt][3] = __float_as_uint(Asb[(r + 8) * 36 + kk + gc + 4]);
            }
            uint32_t b[8][2];
#pragma unroll
            for (int nt = 0; nt < 8; ++nt) {
                const int n = wn * 64 + nt * 8 + gr;
                b[nt][0] = __float_as_uint(Bsb[(kk + gc) * 136 + n]);
                b[nt][1] = __float_as_uint(Bsb[(kk + gc + 4) * 136 + n]);
            }
#pragma unroll
            for (int mt = 0; mt < 2; ++mt)
#pragma unroll
                for (int nt = 0; nt < 8; ++nt)
                    mma_tf32(c[mt][nt], a[mt], b[nt]);
        }
        __syncthreads();
    }

#pragma unroll
    for (int mt = 0; mt < 2; ++mt) {
        const int r0 = mtile + wm * 32 + mt * 16 + gr;
#pragma unroll
        for (int nt = 0; nt < 8; ++nt) {
            const int col = ntile + wn * 64 + nt * 8 + gc * 2;
            const float bz0 = bias[col], bz1 = bias[col + 1];
#pragma unroll
            for (int half = 0; half < 2; ++half) {
                const int row = r0 + half * 8;
                float2 v = make_float2(c[mt][nt][2 * half + 0] + bz0,
                                       c[mt][nt][2 * half + 1] + bz1);
                *(float2*)&Out[(size_t)row * N + col] = v;
            }
        }
    }
}

// ---------------------------------------------------------------------------
extern "C" void kernel_launch(void* const* d_in, const int* in_sizes, int n_in,
                              void* d_out, int out_size)
{
    const float* x     = (const float*)d_in[0];
    const float* W_qkv = (const float*)d_in[1];
    const float* b_qkv = (const float*)d_in[2];
    const float* W_out = (const float*)d_in[3];
    const float* b_out = (const float*)d_in[4];
    float* out = (float*)d_out;

    cudaFuncSetAttribute(gemm_qkv_tc, cudaFuncAttributeMaxDynamicSharedMemorySize,
                         GEMM_SMEM_BYTES);
    cudaFuncSetAttribute(attn_tc_kernel, cudaFuncAttributeMaxDynamicSharedMemorySize,
                         ATTN_SMEM_BYTES);
    cudaFuncSetAttribute(gemm_out_tc, cudaFuncAttributeMaxDynamicSharedMemorySize,
                         GEMM_SMEM_BYTES);

    float* d_xr;    cudaGetSymbolAddress((void**)&d_xr, g_xr);
    float* d_wqkvr; cudaGetSymbolAddress((void**)&d_wqkvr, g_wqkvr);
    float* d_woutr; cudaGetSymbolAddress((void**)&d_woutr, g_woutr);

    // pre-pass: tf32-round X, W_qkv, W_out
    {
        int n4 = MROWS * DD / 4;        // 2,097,152
        round_tf32_kernel<<<(n4 + 255) / 256, 256>>>(x, d_xr, n4);
    }
    {
        int n4 = DD * 3 * DD / 4;       // 786,432
        round_tf32_kernel<<<(n4 + 255) / 256, 256>>>(W_qkv, d_wqkvr, n4);
    }
    {
        int n4 = DD * DD / 4;           // 262,144
        round_tf32_kernel<<<(n4 + 255) / 256, 256>>>(W_out, d_woutr, n4);
    }

    {
        dim3 grid(3 * DD / 128, MROWS / 128);   // (24, 64)
        gemm_qkv_tc<<<grid, 256, GEMM_SMEM_BYTES>>>(b_qkv);
    }
    {
        dim3 grid(TT / 128, BB * HH);           // (16, 64)
        attn_tc_kernel<<<grid, 256, ATTN_SMEM_BYTES>>>();
    }
    {
        dim3 grid(DD / 128, MROWS / 128);       // (8, 64)
        gemm_out_tc<<<grid, 256, GEMM_SMEM_BYTES>>>(b_out, out);
    }
}